// round 17
// baseline (speedup 1.0000x reference)
#include <cuda_runtime.h>
#include <math.h>

#define DD 1024
#define GBK 16
#define SAS 68   // padded smem row stride (floats): 16B-aligned, 2-way staging conflicts
#define NW 48    // CSR row width cap (analytic max nnz/row ~21)

// ---------------- static device storage (no allocation allowed) ----------------
static __device__ double d_H[32 * 32];
static __device__ double d_g;
static __device__ float  d_M0[DD * DD];     // dense P (scale 1/(2*HBAR))
static __device__ float  d_M1[DD * DD];     // Horner ping / U
static __device__ float  d_M3[DD * DD];     // Horner pong / E / ping
static __device__ int    d_cidx[DD * NW];
static __device__ float  d_cval[DD * NW];
static __device__ int    d_cnt[DD];
static __device__ float  d_ua[DD];
static __device__ float  d_ub[DD];
static __device__ float  d_Arows[2048 * DD];

// ---------------- model: H on reduced 32-dim space ----------------
__device__ __forceinline__ double qmat(int r, int c) {
    if (c == r + 1) return sqrt((double)c * 0.5);
    if (r == c + 1) return sqrt((double)r * 0.5);
    return 0.0;
}

__global__ void k_build_H(const float* log_g) {
    int a = threadIdx.x;
    if (a == 0) d_g = (double)expf(log_g[0]);
    int i = a >> 5, j = a & 31;
    int si = i >> 4, vi = i & 15, v6i = vi >> 2, v10i = vi & 3;
    int sj = j >> 4, vj = j & 15, v6j = vj >> 2, v10j = vj & 3;
    const double CM2EV = 0.00012398419;
    const double E_S1 = 3.995, E_S2 = 4.9183;
    const double om6a = 596.0 * CM2EV, om10a = 919.0 * CM2EV;
    const double kap1 = -0.0964, kap2 = 0.1193;
    const double lam = 0.1825, gam = -0.018;
    double val = 0.0;
    if (si == sj) {
        if (vi == vj) val += (si == 0 ? E_S1 : E_S2) + om6a * v6i + om10a * v10i;
        if (v10i == v10j) val += (si == 0 ? kap1 : kap2) * qmat(v6i, v6j);
    } else {
        if (v6i == v6j) {
            double q2 = 0.0;
            #pragma unroll
            for (int m = 0; m < 4; m++) q2 += qmat(v10i, m) * qmat(m, v10j);
            val += lam * qmat(v10i, v10j) + gam * q2;
        }
    }
    d_H[i * 32 + j] = val;
}

// ---------------- real hermitian basis bookkeeping ----------------
__device__ __forceinline__ void decode_basis(int m, int& type, int& p, int& q) {
    if (m < 32) { type = 0; p = q = m; return; }
    int pi = (m < 528) ? (m - 32) : (m - 528);
    type = (m < 528) ? 1 : 2;
    int r = 0, cnt = 31;
    while (pi >= cnt) { pi -= cnt; r++; cnt--; }
    p = r; q = r + 1 + pi;
}

// Fused build of P[m,n]; scale = (DT/HBAR)/2  (s=1 squaring; Horner degree 16)
__global__ void k_buildP() {
    int m = blockIdx.x;
    int n = threadIdx.x;
    int tm, i, j;
    decode_basis(m, tm, i, j);
    int tn, p, q;
    decode_basis(n, tn, p, q);
    int a = i, b = j;
    double v = (tn == 0) ? 1.0 : 0.70710678118654752440;
    int nc = (tn == 0) ? 1 : 2;
    int cc[2] = { p, q };
    int dd[2] = { q, p };
    double ww[2] = { v, (tn == 2) ? -v : v };

    const double g = d_g;
    double HX = 0.0, XH = 0.0, Xab = 0.0, X16 = 0.0;
    for (int e = 0; e < nc; e++) {
        if (dd[e] == b) HX += d_H[a * 32 + cc[e]] * ww[e];
        if (cc[e] == a) XH += ww[e] * d_H[dd[e] * 32 + b];
        if (cc[e] == a && dd[e] == b) Xab += ww[e];
        if (a < 16 && b < 16 && cc[e] == a + 16 && dd[e] == b + 16) X16 += ww[e];
    }
    double diss = g * (X16 - 0.5 * Xab * (double)((a >= 16) + (b >= 16)));
    double cs, ca;
    if (tn == 2) { cs = XH - HX; ca = diss; }
    else         { ca = HX - XH; cs = diss; }

    const double SQ2 = 1.41421356237309504880;
    double val;
    if (tm == 0)      val = cs;
    else if (tm == 1) val = SQ2 * cs;
    else              val = SQ2 * ca;
    const double scale = (1.0 / 0.6582119569) / 2.0;
    d_M0[m * DD + n] = (float)(val * scale);
}

// ---------------- CSR build (deterministic ballot-scan compaction) ----------------
__global__ void k_tocsr() {
    int m = blockIdx.x;
    int n = threadIdx.x;
    float v = d_M0[m * DD + n];
    bool nz = (v != 0.0f);
    unsigned mask = __ballot_sync(0xffffffffu, nz);
    int lane = n & 31, w = n >> 5;
    __shared__ int wcnt[32];
    __shared__ int woff[32];
    __shared__ int tot;
    if (lane == 0) wcnt[w] = __popc(mask);
    __syncthreads();
    if (n == 0) {
        int s = 0;
        for (int i = 0; i < 32; i++) { woff[i] = s; s += wcnt[i]; }
        tot = (s > NW) ? NW : s;
        d_cnt[m] = tot;
    }
    __syncthreads();
    if (nz) {
        int pos = woff[w] + __popc(mask & ((1u << lane) - 1u));
        if (pos < NW) {
            d_cidx[m * NW + pos] = n;
            d_cval[m * NW + pos] = v;
        }
    }
    if (n >= tot && n < NW) {
        d_cidx[m * NW + n] = 0;
        d_cval[m * NW + n] = 0.0f;
    }
}

// T0 = I + P/16  (Horner init)
__global__ void k_hinit(float* __restrict__ T) {
    int idx = blockIdx.x * 1024 + threadIdx.x;
    int r = idx >> 10, c = idx & 1023;
    float x = d_M0[idx] * (1.0f / 16.0f);
    if (r == c) x += 1.0f;
    T[idx] = x;
}

// Horner step: Y = I + (P @ X) / k   (P sparse, CSR rows; ascending-n order)
__global__ void __launch_bounds__(256) k_spmm(
    const float* __restrict__ X, float* __restrict__ Y, float invk)
{
    int m = blockIdx.x;
    int t = threadIdx.x;
    __shared__ int   sidx[NW];
    __shared__ float sval[NW];
    __shared__ int   scnt;
    if (t < NW) { sidx[t] = d_cidx[m * NW + t]; sval[t] = d_cval[m * NW + t]; }
    if (t == 0) scnt = d_cnt[m];
    __syncthreads();
    int cnt = scnt;
    int c = t * 4;
    float4 acc = make_float4(0.f, 0.f, 0.f, 0.f);
    for (int e = 0; e < cnt; e++) {
        float v = sval[e];
        const float4 x = *(const float4*)&X[(size_t)sidx[e] * DD + c];
        acc.x = fmaf(v, x.x, acc.x);
        acc.y = fmaf(v, x.y, acc.y);
        acc.z = fmaf(v, x.z, acc.z);
        acc.w = fmaf(v, x.w, acc.w);
    }
    float4 y = make_float4(acc.x * invk, acc.y * invk, acc.z * invk, acc.w * invk);
    int d = m - c;
    if (d >= 0 && d < 4) ((float*)&y)[d] += 1.0f;
    *(float4*)&Y[(size_t)m * DD + c] = y;
}

__global__ void k_Ainit() {
    int r = blockIdx.x, c = threadIdx.x;
    float v = 0.0f;
    if (r == 0 && c < 16) v = 1.0f;
    if (r == 1 && c >= 16 && c < 32) v = 1.0f;
    d_Arows[r * DD + c] = v;
}

__global__ void k_extract(float* __restrict__ out, int n) {
    int t = blockIdx.x * blockDim.x + threadIdx.x;
    if (t >= n) return;
    out[t] = 0.0f;
    out[n + t]     = d_Arows[(size_t)(2 * t) * DD + 16];
    out[2 * n + t] = d_Arows[(size_t)(2 * t + 1) * DD + 16];
}

// ---------------- packed f32x2 / async helpers ----------------
__device__ __forceinline__ void ffma2(unsigned long long& acc,
                                      unsigned long long a, unsigned long long b) {
    asm("fma.rn.f32x2 %0, %1, %2, %0;" : "+l"(acc) : "l"(a), "l"(b));
}
__device__ __forceinline__ unsigned long long pack2(float x) {
    unsigned long long r; unsigned u = __float_as_uint(x);
    asm("mov.b64 %0, {%1, %1};" : "=l"(r) : "r"(u));
    return r;
}
__device__ __forceinline__ void unpack2(unsigned long long v, float& lo, float& hi) {
    unsigned a, b;
    asm("mov.b64 {%0, %1}, %2;" : "=r"(a), "=r"(b) : "l"(v));
    lo = __uint_as_float(a); hi = __uint_as_float(b);
}
__device__ __forceinline__ void cpa16(unsigned dst, const void* src) {
    asm volatile("cp.async.ca.shared.global [%0], [%1], 16;" :: "r"(dst), "l"(src));
}
__device__ __forceinline__ void cpa_commit() {
    asm volatile("cp.async.commit_group;" ::: "memory");
}
__device__ __forceinline__ void cpa_wait0() {
    asm volatile("cp.async.wait_group 0;" ::: "memory");
}

// ---------------- dense GEMM: C(MxDD)=A@B; 64x64 tile; 512 thr = 2 K-teams ----------------
// Async-pipelined staging: B via cp.async (no reg/dep cost), A via LDG-to-regs
// issued BEFORE the compute block and STS'd AFTER it, so the ~250cyc L2 latency
// is covered by the 16-kk FFMA2 block. Staged smem contents, inner loop, and
// split-K combine are byte-identical to the round-16 engine.
__device__ __forceinline__ void gemm_tile512(
    const float* __restrict__ A, const float* __restrict__ B, float* __restrict__ C,
    int M, int row0, int bx)
{
    __shared__ float smem[2 * 2 * 2 * GBK * SAS];   // [buf][team][A|B][k][SAS] = 34.8KB
    const int TEAMSZ = 2 * GBK * SAS;
    const int BUFSZ = 2 * TEAMSZ;
    float* pad = smem;                               // combine pad aliases buffer 0
    int tid = threadIdx.x;
    int team = tid >> 8;
    int t = tid & 255;
    int tx = ((t >> 5) & 1) * 8 + (t & 7);
    int ty = (t >> 6) * 4 + ((t >> 3) & 3);
    int k0 = team << 9;
    int ar = t >> 2, akc = t & 3;
    int bk = t >> 4, bnc = t & 15;
    bool arow_ok = (row0 + ar < M);
    const float* Ap = &A[(size_t)(row0 + (arow_ok ? ar : 0)) * DD + k0 + akc * 4];
    const float* Bp = &B[(size_t)(k0 + bk) * DD + bx * 64 + bnc * 4];

    float* sAb[2]; float* sBb[2];
    sAb[0] = smem + team * TEAMSZ;          sBb[0] = sAb[0] + GBK * SAS;
    sAb[1] = smem + BUFSZ + team * TEAMSZ;  sBb[1] = sAb[1] + GBK * SAS;
    unsigned sBdst[2];
    sBdst[0] = (unsigned)__cvta_generic_to_shared(sBb[0] + bk * SAS + bnc * 4);
    sBdst[1] = (unsigned)__cvta_generic_to_shared(sBb[1] + bk * SAS + bnc * 4);

    unsigned long long acc[4][2];
    #pragma unroll
    for (int i = 0; i < 4; i++) { acc[i][0] = 0ULL; acc[i][1] = 0ULL; }

    {   // prologue: slab 0 into buffer 0
        float4 va = make_float4(0.f, 0.f, 0.f, 0.f);
        if (arow_ok) va = *(const float4*)Ap;
        cpa16(sBdst[0], Bp);
        cpa_commit();
        sAb[0][(akc * 4 + 0) * SAS + ar] = va.x;
        sAb[0][(akc * 4 + 1) * SAS + ar] = va.y;
        sAb[0][(akc * 4 + 2) * SAS + ar] = va.z;
        sAb[0][(akc * 4 + 3) * SAS + ar] = va.w;
        cpa_wait0();
        __syncthreads();
    }

    for (int it = 0; it < 32; it++) {
        int buf = it & 1;
        float4 vn = make_float4(0.f, 0.f, 0.f, 0.f);
        if (it < 31) {   // issue next-slab loads BEFORE compute
            if (arow_ok) vn = *(const float4*)(Ap + (it + 1) * GBK);
            cpa16(sBdst[buf ^ 1], Bp + (size_t)(it + 1) * GBK * DD);
            cpa_commit();
        }
        float* sA = sAb[buf];
        float* sB = sBb[buf];
        #pragma unroll
        for (int kk = 0; kk < GBK; kk++) {
            float4 av = *(const float4*)&sA[kk * SAS + ty * 4];
            ulonglong2 bv = *(const ulonglong2*)&sB[kk * SAS + tx * 4];
            unsigned long long a0 = pack2(av.x), a1 = pack2(av.y),
                               a2 = pack2(av.z), a3 = pack2(av.w);
            ffma2(acc[0][0], a0, bv.x); ffma2(acc[0][1], a0, bv.y);
            ffma2(acc[1][0], a1, bv.x); ffma2(acc[1][1], a1, bv.y);
            ffma2(acc[2][0], a2, bv.x); ffma2(acc[2][1], a2, bv.y);
            ffma2(acc[3][0], a3, bv.x); ffma2(acc[3][1], a3, bv.y);
        }
        if (it < 31) {   // deposit prefetched A AFTER compute (latency covered)
            float* dA = sAb[buf ^ 1];
            dA[(akc * 4 + 0) * SAS + ar] = vn.x;
            dA[(akc * 4 + 1) * SAS + ar] = vn.y;
            dA[(akc * 4 + 2) * SAS + ar] = vn.z;
            dA[(akc * 4 + 3) * SAS + ar] = vn.w;
            cpa_wait0();
        }
        __syncthreads();
    }

    // combine: team 1 deposits partials, team 0 adds (deterministic lo+hi)
    if (team == 1) {
        #pragma unroll
        for (int i = 0; i < 4; i++) {
            float v[4];
            unpack2(acc[i][0], v[0], v[1]);
            unpack2(acc[i][1], v[2], v[3]);
            *(float4*)&pad[(ty * 4 + i) * 64 + tx * 4] = make_float4(v[0], v[1], v[2], v[3]);
        }
    }
    __syncthreads();
    if (team == 0) {
        #pragma unroll
        for (int i = 0; i < 4; i++) {
            int r = row0 + ty * 4 + i;
            if (r >= M) continue;
            float v[4];
            unpack2(acc[i][0], v[0], v[1]);
            unpack2(acc[i][1], v[2], v[3]);
            float4 pv = *(const float4*)&pad[(ty * 4 + i) * 64 + tx * 4];
            v[0] += pv.x; v[1] += pv.y; v[2] += pv.z; v[3] += pv.w;
            *(float4*)&C[(size_t)r * DD + bx * 64 + tx * 4] =
                make_float4(v[0], v[1], v[2], v[3]);
        }
    }
}

__global__ void __launch_bounds__(512, 2) k_gemm512(
    const float* __restrict__ A, const float* __restrict__ B, float* __restrict__ C, int M)
{
    gemm_tile512(A, B, C, M, blockIdx.y * 64, blockIdx.x);
}

// fused: by<16 squares (Bn = Bc@Bc); by>=16 doubles rows (Adst = Ar@Bc)
__global__ void __launch_bounds__(512, 2) k_sq_dbl512(
    const float* __restrict__ Bc, float* __restrict__ Bn,
    const float* __restrict__ Ar, float* __restrict__ Adst, int rows)
{
    if (blockIdx.y < 16)
        gemm_tile512(Bc, Bc, Bn, DD, blockIdx.y * 64, blockIdx.x);
    else
        gemm_tile512(Ar, Bc, Adst, rows, (blockIdx.y - 16) * 64, blockIdx.x);
}

__global__ void k_getcol(const float* __restrict__ Bc, float* __restrict__ u) {
    u[threadIdx.x] = Bc[(size_t)threadIdx.x * DD + 16];
}

// fused tail step: blocks [0,256) col-16 gemv; blocks [256,1280) matvec row.
__global__ void __launch_bounds__(256) k_tail(
    const float* __restrict__ Bc, const float* __restrict__ u,
    float* __restrict__ u_out, int ofs)
{
    __shared__ float red[256];
    int b = blockIdx.x, t = threadIdx.x;
    const float* row = (b < 256) ? &d_Arows[(size_t)b * DD]
                                 : &Bc[(size_t)(b - 256) * DD];
    float s = 0.0f;
    for (int k = t; k < DD; k += 256)
        s = fmaf(row[k], u[k], s);
    red[t] = s;
    __syncthreads();
    for (int w = 128; w > 0; w >>= 1) {
        if (t < w) red[t] += red[t + w];
        __syncthreads();
    }
    if (t == 0) {
        if (b < 256) d_Arows[(size_t)(ofs + b) * DD + 16] = red[0];
        else         u_out[b - 256] = red[0];
    }
}

// ---------------- driver ----------------
extern "C" void kernel_launch(void* const* d_in, const int* in_sizes, int n_in,
                              void* d_out, int out_size) {
    const float* log_g = (const float*)d_in[0];
    int n_steps = out_size / 3;
    if (n_steps < 1) n_steps = 1;
    if (n_steps > 1024) n_steps = 1024;

    void *p1, *p3, *pA, *pua, *pub;
    cudaGetSymbolAddress(&p1, d_M1);
    cudaGetSymbolAddress(&p3, d_M3);
    cudaGetSymbolAddress(&pA, d_Arows);
    cudaGetSymbolAddress(&pua, d_ua);
    cudaGetSymbolAddress(&pub, d_ub);
    float *M1 = (float*)p1, *M3 = (float*)p3, *Ar = (float*)pA;
    float *ua = (float*)pua, *ub = (float*)pub;

    // Phase 0: build generator P (fp32, scale 1/(2*HBAR)) directly; compress to CSR
    k_build_H<<<1, 1024>>>(log_g);
    k_buildP<<<1024, 1024>>>();
    k_tocsr<<<1024, 1024>>>();

    // Phase 1: E = expm(P) via degree-16 Horner with SPARSE P, then U = E^2
    k_hinit<<<1024, 1024>>>(M1);                 // T = I + P/16
    float* Tc = M1; float* Tn = M3;
    for (int k = 15; k >= 1; k--) {
        k_spmm<<<1024, 256>>>(Tc, Tn, 1.0f / (float)k);
        float* tmp = Tc; Tc = Tn; Tn = tmp;
    }
    dim3 gfull(16, 16);
    k_gemm512<<<gfull, 512>>>(Tc, Tc, Tn, DD);   // U -> Tn
    float* Bc = Tn;
    float* Bn = Tc;

    // Phase 2: time doubling up to 256 rows (times 0..127), 7 fused iterations
    k_Ainit<<<2, 1024>>>();
    int rows = 2;
    for (int kd = 0; kd < 7; kd++) {
        int dbl_tiles = (rows + 63) / 64;
        k_sq_dbl512<<<dim3(16, 16 + dbl_tiles), 512>>>(
            Bc, Bn, Ar, Ar + (size_t)rows * DD, rows);
        rows <<= 1;
        float* tmp = Bc; Bc = Bn; Bn = tmp;
    }
    // Bc = U^128, rows = 256 (times 0..127 fully materialized)

    // Phase 3: tail — times 128..1023 need only column 16.
    k_getcol<<<1, 1024>>>(Bc, ua);
    float* ucur = ua;
    float* unxt = ub;
    for (int k = 1; k <= 7; k++) {
        int nblocks = (k < 7) ? 1280 : 256;
        k_tail<<<nblocks, 256>>>(Bc, ucur, unxt, 256 * k);
        float* tmp = ucur; ucur = unxt; unxt = tmp;
    }

    // Phase 4: extract populations
    k_extract<<<(n_steps + 255) / 256, 256>>>((float*)d_out, n_steps);
}